// round 10
// baseline (speedup 1.0000x reference)
#include <cuda_runtime.h>
#include <cuda_fp16.h>
#include <cstdint>

// Problem constants
#define B    32
#define SW   512
#define SL   256
#define H    768
#define NL   4
#define NOUT 400
#define NWORDS (B * SL)          // 8192
#define H4   (H / 4)             // 192 float4 per row

// ---------------- scratch (static device globals; no allocations) ------------
__device__ __half g_Ah[NWORDS * H];        // pooled fp16 (12.6 MB)
__device__ __half g_Bh[NOUT * H];          // proj_w fp16
__device__ int    g_starts[B * SL];
__device__ float  g_w[NL];

// =============================================================================
// Kernel 1a: prep — lens scan + softmax weights only (tiny).
// =============================================================================
__global__ __launch_bounds__(SL) void prep_kernel(
    const int* __restrict__ lens, const float* __restrict__ mixw,
    const float* __restrict__ gamma)
{
    const int b = blockIdx.x;
    const int t = threadIdx.x;
    __shared__ int s[SL];

    const int l = lens[(b << 8) + t];
    s[t] = l;
    __syncthreads();
#pragma unroll
    for (int off = 1; off < SL; off <<= 1) {
        int x = (t >= off) ? s[t - off] : 0;
        __syncthreads();
        s[t] += x;
        __syncthreads();
    }
    g_starts[(b << 8) + t] = s[t] - l;

    if (b == 0 && t == 0) {
        float mw0 = mixw[0], mw1 = mixw[1], mw2 = mixw[2], mw3 = mixw[3];
        float mx = fmaxf(fmaxf(mw0, mw1), fmaxf(mw2, mw3));
        float e0 = __expf(mw0 - mx), e1 = __expf(mw1 - mx);
        float e2 = __expf(mw2 - mx), e3 = __expf(mw3 - mx);
        float inv = gamma[0] / (e0 + e1 + e2 + e3);
        g_w[0] = e0 * inv; g_w[1] = e1 * inv; g_w[2] = e2 * inv; g_w[3] = e3 * inv;
    }
}

// =============================================================================
// Kernel 1b: conv — proj_w -> fp16, one float4 per thread (300 blocks x 256).
// =============================================================================
__global__ __launch_bounds__(256) void conv_kernel(const float* __restrict__ projw)
{
    const int i = blockIdx.x * 256 + threadIdx.x;   // < 76800 exactly
    float4 v = ((const float4*)projw)[i];
    __half2 p0 = __floats2half2_rn(v.x, v.y);
    __half2 p1 = __floats2half2_rn(v.z, v.w);
    uint2 pk;
    pk.x = *(uint32_t*)&p0;
    pk.y = *(uint32_t*)&p1;
    ((uint2*)g_Bh)[i] = pk;
}

// =============================================================================
// Kernel 2: pool — mix + ragged mean, emit fp16 rows.
// One block per word, 192 threads (one float4 column slice each).
// =============================================================================
__global__ __launch_bounds__(H4) void pool_kernel(
    const float* __restrict__ hs, const int* __restrict__ lens)
{
    const int wi = blockIdx.x;
    const int b  = wi >> 8;
    const int h4 = threadIdx.x;            // 0..191

    const int len   = lens[wi];
    const int start = g_starts[wi];
    const int end   = min(start + len, SW);

    const float w0 = g_w[0], w1 = g_w[1], w2 = g_w[2], w3 = g_w[3];
    const size_t lstride4 = (size_t)B * SW * H4;

    float4 acc = make_float4(0.f, 0.f, 0.f, 0.f);
    for (int p = start; p < end; p++) {
        const float4* base = (const float4*)hs + ((size_t)b * SW + p) * H4 + h4;
        float4 v0 = base[0 * lstride4];
        float4 v1 = base[1 * lstride4];
        float4 v2 = base[2 * lstride4];
        float4 v3 = base[3 * lstride4];
        acc.x += w0 * v0.x + w1 * v1.x + w2 * v2.x + w3 * v3.x;
        acc.y += w0 * v0.y + w1 * v1.y + w2 * v2.y + w3 * v3.y;
        acc.z += w0 * v0.z + w1 * v1.z + w2 * v2.z + w3 * v3.z;
        acc.w += w0 * v0.w + w1 * v1.w + w2 * v2.w + w3 * v3.w;
    }
    const float inv = 1.0f / (float)max(len, 1);

    __half2 p0 = __floats2half2_rn(acc.x * inv, acc.y * inv);
    __half2 p1 = __floats2half2_rn(acc.z * inv, acc.w * inv);
    uint2 pk;
    pk.x = *(uint32_t*)&p0;
    pk.y = *(uint32_t*)&p1;
    ((uint2*)g_Ah)[(size_t)wi * 192 + h4] = pk;
}

// =============================================================================
// Kernel 3: GEMM out[8192,400] = A[8192,768]fp16 @ W[400,768]^T fp16, fp32 acc.
// mma.sync m16n8k16 + ldmatrix + cp.async double buffering.
// BM=128, BN=80, BK=48 (16 stages), 256 threads (8 warps 4x2).
// Padded smem stride 56 halfs (112B) -> conflict-free ldmatrix phases.
// Exact tiling: grid (64, 5). smem 46.6KB static (2 buffers).
// =============================================================================
#define BK 48
#define ASTR 56                             // fp16 stride (112B)
#define NSTAGE (H / BK)                     // 16

__device__ __forceinline__ uint32_t smem_u32(const void* p) {
    uint32_t a;
    asm("{ .reg .u64 t; cvta.to.shared.u64 t, %1; cvt.u32.u64 %0, t; }" : "=r"(a) : "l"(p));
    return a;
}
__device__ __forceinline__ void ldm_x4(uint32_t* r, uint32_t addr) {
    asm volatile("ldmatrix.sync.aligned.m8n8.x4.shared.b16 {%0,%1,%2,%3}, [%4];"
        : "=r"(r[0]), "=r"(r[1]), "=r"(r[2]), "=r"(r[3]) : "r"(addr));
}
__device__ __forceinline__ void ldm_x2(uint32_t* r, uint32_t addr) {
    asm volatile("ldmatrix.sync.aligned.m8n8.x2.shared.b16 {%0,%1}, [%2];"
        : "=r"(r[0]), "=r"(r[1]) : "r"(addr));
}
__device__ __forceinline__ void mma_f16(float* d, const uint32_t* a, const uint32_t* b) {
    asm volatile(
        "mma.sync.aligned.m16n8k16.row.col.f32.f16.f16.f32 "
        "{%0,%1,%2,%3}, {%4,%5,%6,%7}, {%8,%9}, {%0,%1,%2,%3};"
        : "+f"(d[0]), "+f"(d[1]), "+f"(d[2]), "+f"(d[3])
        : "r"(a[0]), "r"(a[1]), "r"(a[2]), "r"(a[3]), "r"(b[0]), "r"(b[1]));
}
__device__ __forceinline__ void cpa16(uint32_t saddr, const void* g) {
    asm volatile("cp.async.cg.shared.global [%0], [%1], 16;" :: "r"(saddr), "l"(g) : "memory");
}
__device__ __forceinline__ void cpa_commit() {
    asm volatile("cp.async.commit_group;" ::: "memory");
}

__global__ __launch_bounds__(256) void gemm_kernel(float* __restrict__ out)
{
    __shared__ __half As[2][128][ASTR];     // 2 * 14336 B
    __shared__ __half Bs[2][80][ASTR];      // 2 *  8960 B   -> 46592 total

    const int tid  = threadIdx.x;
    const int lane = tid & 31;
    const int warp = tid >> 5;
    const int wm   = warp & 3;             // 0..3 -> 32-row slice
    const int wn   = warp >> 2;            // 0..1 -> 40-col slice
    const int m0   = blockIdx.x * 128;
    const int n0   = blockIdx.y * 80;

    const int g  = lane >> 2;
    const int tg = lane & 3;

    const uint32_t as_base = smem_u32(As);
    const uint32_t bs_base = smem_u32(Bs);
    const uint32_t a_sz = 128 * ASTR * 2;  // bytes per A buffer
    const uint32_t b_sz = 80 * ASTR * 2;

    // per-lane ldmatrix base addresses (k/buffer offsets added in loop)
    const int a_row = wm * 32 + (lane & 15);
    const uint32_t a_addr0 = as_base + ((a_row)      * ASTR + (lane >> 4) * 8) * 2;
    const uint32_t a_addr1 = as_base + ((a_row + 16) * ASTR + (lane >> 4) * 8) * 2;
    const int b_row = wn * 40 + (lane & 7);
    const uint32_t b_addr = bs_base + (b_row * ASTR + ((lane >> 3) & 1) * 8) * 2;

    float acc[2][5][4];
#pragma unroll
    for (int mi = 0; mi < 2; mi++)
#pragma unroll
        for (int ni = 0; ni < 5; ni++)
#pragma unroll
            for (int r = 0; r < 4; r++) acc[mi][ni][r] = 0.f;

    const uint4* Ag = (const uint4*)g_Ah;  // row stride 96 uint4
    const uint4* Bg = (const uint4*)g_Bh;

    // ---- async stage loader: A 128x6 uint4 (768), B 80x6 uint4 (480) ----
    auto load_stage = [&](int s, int buf) {
        const int k0u = s * 6;             // BK/8 uint4 per stage
        const uint32_t ab = as_base + buf * a_sz;
        const uint32_t bb = bs_base + buf * b_sz;
#pragma unroll
        for (int i = 0; i < 3; i++) {
            int e = tid + i * 256;         // < 768
            int r = e / 6, c = e - r * 6;
            cpa16(ab + (r * ASTR + c * 8) * 2, Ag + (size_t)(m0 + r) * 96 + k0u + c);
        }
#pragma unroll
        for (int i = 0; i < 2; i++) {
            int e = tid + i * 256;
            if (e < 480) {
                int r = e / 6, c = e - r * 6;
                cpa16(bb + (r * ASTR + c * 8) * 2, Bg + (size_t)(n0 + r) * 96 + k0u + c);
            }
        }
        cpa_commit();
    };

    load_stage(0, 0);

    for (int s = 0; s < NSTAGE; s++) {
        if (s + 1 < NSTAGE) {
            load_stage(s + 1, (s + 1) & 1);
            asm volatile("cp.async.wait_group 1;" ::: "memory");
        } else {
            asm volatile("cp.async.wait_group 0;" ::: "memory");
        }
        __syncthreads();

        const uint32_t abuf = (uint32_t)(s & 1) * a_sz;
        const uint32_t bbuf = (uint32_t)(s & 1) * b_sz;
#pragma unroll
        for (int kk = 0; kk < BK; kk += 16) {
            uint32_t afr[2][4], bfr[5][2];
            ldm_x4(afr[0], a_addr0 + abuf + kk * 2);
            ldm_x4(afr[1], a_addr1 + abuf + kk * 2);
#pragma unroll
            for (int ni = 0; ni < 5; ni++)
                ldm_x2(bfr[ni], b_addr + bbuf + (ni * 8 * ASTR + kk) * 2);
#pragma unroll
            for (int mi = 0; mi < 2; mi++)
#pragma unroll
                for (int ni = 0; ni < 5; ni++)
                    mma_f16(acc[mi][ni], afr[mi], bfr[ni]);
        }
        __syncthreads();
    }

    // ---- epilogue: float2 stores, all indices in-bounds by construction ----
#pragma unroll
    for (int mi = 0; mi < 2; mi++) {
#pragma unroll
        for (int ni = 0; ni < 5; ni++) {
            int r = m0 + wm * 32 + mi * 16 + g;
            int c = n0 + wn * 40 + ni * 8 + tg * 2;
            *(float2*)(out + (size_t)r * NOUT + c) =
                make_float2(acc[mi][ni][0], acc[mi][ni][1]);
            *(float2*)(out + (size_t)(r + 8) * NOUT + c) =
                make_float2(acc[mi][ni][2], acc[mi][ni][3]);
        }
    }
}

// =============================================================================
// launch
// =============================================================================
extern "C" void kernel_launch(void* const* d_in, const int* in_sizes, int n_in,
                              void* d_out, int out_size) {
    // metadata order: subwords, bert_lens, bert_mask, hidden_states,
    //                 mix_weights, gamma, proj_w
    const int*   lens  = (const int*)d_in[1];
    const float* hs    = (const float*)d_in[3];
    const float* mixw  = (const float*)d_in[4];
    const float* gamma = (const float*)d_in[5];
    const float* projw = (const float*)d_in[6];
    float*       out   = (float*)d_out;

    prep_kernel<<<B, SL>>>(lens, mixw, gamma);
    conv_kernel<<<NOUT * H / 4 / 256, 256>>>(projw);
    pool_kernel<<<NWORDS, H4>>>(hs, lens);
    gemm_kernel<<<dim3(NWORDS / 128, NOUT / 80), 256>>>(out);
}

// round 12
// speedup vs baseline: 1.1060x; 1.1060x over previous
#include <cuda_runtime.h>
#include <cuda_fp16.h>
#include <cstdint>

// Problem constants
#define B    32
#define SW   512
#define SL   256
#define H    768
#define NL   4
#define NOUT 400
#define NWORDS (B * SL)          // 8192
#define H4   (H / 4)             // 192 float4 per row

// ---------------- scratch (static device globals; no allocations) ------------
__device__ __half g_Ah[NWORDS * H];        // pooled fp16 (12.6 MB)
__device__ __half g_Bh[NOUT * H];          // proj_w fp16
__device__ int    g_starts[B * SL];
__device__ float  g_w[NL];

// =============================================================================
// Kernel 1: prep+conv fused. Blocks 0..31: lens scan + softmax weights.
// Blocks 32..331: proj_w -> fp16 (one float4/thread, 76800 exactly).
// =============================================================================
__global__ __launch_bounds__(256) void prep_kernel(
    const int* __restrict__ lens, const float* __restrict__ mixw,
    const float* __restrict__ gamma, const float* __restrict__ projw)
{
    const int blk = blockIdx.x;
    const int t = threadIdx.x;

    if (blk >= 32) {                       // ---- conv part ----
        const int i = (blk - 32) * 256 + t;
        float4 v = ((const float4*)projw)[i];
        __half2 p0 = __floats2half2_rn(v.x, v.y);
        __half2 p1 = __floats2half2_rn(v.z, v.w);
        uint2 pk;
        pk.x = *(uint32_t*)&p0;
        pk.y = *(uint32_t*)&p1;
        ((uint2*)g_Bh)[i] = pk;
        return;
    }

    // ---- scan part ----
    const int b = blk;
    __shared__ int s[SL];
    const int l = lens[(b << 8) + t];
    s[t] = l;
    __syncthreads();
#pragma unroll
    for (int off = 1; off < SL; off <<= 1) {
        int x = (t >= off) ? s[t - off] : 0;
        __syncthreads();
        s[t] += x;
        __syncthreads();
    }
    g_starts[(b << 8) + t] = s[t] - l;

    if (b == 0 && t == 0) {
        float mw0 = mixw[0], mw1 = mixw[1], mw2 = mixw[2], mw3 = mixw[3];
        float mx = fmaxf(fmaxf(mw0, mw1), fmaxf(mw2, mw3));
        float e0 = __expf(mw0 - mx), e1 = __expf(mw1 - mx);
        float e2 = __expf(mw2 - mx), e3 = __expf(mw3 - mx);
        float inv = gamma[0] / (e0 + e1 + e2 + e3);
        g_w[0] = e0 * inv; g_w[1] = e1 * inv; g_w[2] = e2 * inv; g_w[3] = e3 * inv;
    }
}

// =============================================================================
// Kernel 2: pool — mix + ragged mean, emit fp16 rows.
// One block per word, 192 threads (one float4 column slice each).
// =============================================================================
__global__ __launch_bounds__(H4) void pool_kernel(
    const float* __restrict__ hs, const int* __restrict__ lens)
{
    const int wi = blockIdx.x;
    const int b  = wi >> 8;
    const int h4 = threadIdx.x;            // 0..191

    const int len   = lens[wi];
    const int start = g_starts[wi];
    const int end   = min(start + len, SW);

    const float w0 = g_w[0], w1 = g_w[1], w2 = g_w[2], w3 = g_w[3];
    const size_t lstride4 = (size_t)B * SW * H4;

    float4 acc = make_float4(0.f, 0.f, 0.f, 0.f);
    for (int p = start; p < end; p++) {
        const float4* base = (const float4*)hs + ((size_t)b * SW + p) * H4 + h4;
        float4 v0 = base[0 * lstride4];
        float4 v1 = base[1 * lstride4];
        float4 v2 = base[2 * lstride4];
        float4 v3 = base[3 * lstride4];
        acc.x += w0 * v0.x + w1 * v1.x + w2 * v2.x + w3 * v3.x;
        acc.y += w0 * v0.y + w1 * v1.y + w2 * v2.y + w3 * v3.y;
        acc.z += w0 * v0.z + w1 * v1.z + w2 * v2.z + w3 * v3.z;
        acc.w += w0 * v0.w + w1 * v1.w + w2 * v2.w + w3 * v3.w;
    }
    const float inv = 1.0f / (float)max(len, 1);

    __half2 p0 = __floats2half2_rn(acc.x * inv, acc.y * inv);
    __half2 p1 = __floats2half2_rn(acc.z * inv, acc.w * inv);
    uint2 pk;
    pk.x = *(uint32_t*)&p0;
    pk.y = *(uint32_t*)&p1;
    ((uint2*)g_Ah)[(size_t)wi * 192 + h4] = pk;
}

// =============================================================================
// Kernel 3: GEMM out[8192,400] = A[8192,768]fp16 @ W[400,768]^T fp16, fp32 acc.
// BM=64, BN=80, BK=64, 256 threads (8 warps 4x2: 16 rows x 40 cols each).
// cp.async double buffer (41.5KB smem), launch_bounds(256,4) -> 4 CTAs/SM,
// grid (128,5)=640 CTAs -> whole grid ~resident in one wave.
// Padded stride 72 halfs -> conflict-free ldmatrix. Exact tiling.
// =============================================================================
#define BM 64
#define BK 64
#define ASTR 72                             // fp16 stride (144B)
#define NSTAGE (H / BK)                     // 12

__device__ __forceinline__ uint32_t smem_u32(const void* p) {
    uint32_t a;
    asm("{ .reg .u64 t; cvta.to.shared.u64 t, %1; cvt.u32.u64 %0, t; }" : "=r"(a) : "l"(p));
    return a;
}
__device__ __forceinline__ void ldm_x4(uint32_t* r, uint32_t addr) {
    asm volatile("ldmatrix.sync.aligned.m8n8.x4.shared.b16 {%0,%1,%2,%3}, [%4];"
        : "=r"(r[0]), "=r"(r[1]), "=r"(r[2]), "=r"(r[3]) : "r"(addr));
}
__device__ __forceinline__ void ldm_x2(uint32_t* r, uint32_t addr) {
    asm volatile("ldmatrix.sync.aligned.m8n8.x2.shared.b16 {%0,%1}, [%2];"
        : "=r"(r[0]), "=r"(r[1]) : "r"(addr));
}
__device__ __forceinline__ void mma_f16(float* d, const uint32_t* a, const uint32_t* b) {
    asm volatile(
        "mma.sync.aligned.m16n8k16.row.col.f32.f16.f16.f32 "
        "{%0,%1,%2,%3}, {%4,%5,%6,%7}, {%8,%9}, {%0,%1,%2,%3};"
        : "+f"(d[0]), "+f"(d[1]), "+f"(d[2]), "+f"(d[3])
        : "r"(a[0]), "r"(a[1]), "r"(a[2]), "r"(a[3]), "r"(b[0]), "r"(b[1]));
}
__device__ __forceinline__ void cpa16(uint32_t saddr, const void* g) {
    asm volatile("cp.async.cg.shared.global [%0], [%1], 16;" :: "r"(saddr), "l"(g) : "memory");
}

__global__ __launch_bounds__(256, 4) void gemm_kernel(float* __restrict__ out)
{
    __shared__ __half As[2][BM][ASTR];      // 2 * 9216 B
    __shared__ __half Bs[2][80][ASTR];      // 2 * 11520 B  -> 41472 total

    const int tid  = threadIdx.x;
    const int lane = tid & 31;
    const int warp = tid >> 5;
    const int wm   = warp & 3;             // 0..3 -> 16-row slice
    const int wn   = warp >> 2;            // 0..1 -> 40-col slice
    const int m0   = blockIdx.x * BM;
    const int n0   = blockIdx.y * 80;

    const int g  = lane >> 2;
    const int tg = lane & 3;

    const uint32_t as_base = smem_u32(As);
    const uint32_t bs_base = smem_u32(Bs);
    const uint32_t a_sz = BM * ASTR * 2;   // bytes per A buffer
    const uint32_t b_sz = 80 * ASTR * 2;

    // A fragment addr: rows wm*16 + (lane&15), colblk (lane>>4)*8
    const uint32_t a_addr = as_base +
        (((wm * 16) + (lane & 15)) * ASTR + (lane >> 4) * 8) * 2;
    // B x4 addr (two n-tiles): row = nb + ((lane>>4)&1)*8 + (lane&7),
    //                          colblk = ((lane>>3)&1)*8
    const uint32_t b_addr4 = bs_base +
        ((wn * 40 + ((lane >> 4) & 1) * 8 + (lane & 7)) * ASTR
         + ((lane >> 3) & 1) * 8) * 2;
    // B x2 addr (5th n-tile): row = nb+32 + (lane&7), colblk ((lane>>3)&1)*8
    const uint32_t b_addr2 = bs_base +
        ((wn * 40 + 32 + (lane & 7)) * ASTR + ((lane >> 3) & 1) * 8) * 2;

    float acc[5][4];
#pragma unroll
    for (int ni = 0; ni < 5; ni++)
#pragma unroll
        for (int r = 0; r < 4; r++) acc[ni][r] = 0.f;

    const uint4* Ag = (const uint4*)g_Ah;  // row stride 96 uint4
    const uint4* Bg = (const uint4*)g_Bh;

    // ---- async stage loader: A 64x8 uint4 (512), B 80x8 uint4 (640) ----
    auto load_stage = [&](int s, int buf) {
        const int k0u = s * 8;             // BK/8 uint4 per stage
        const uint32_t ab = as_base + buf * a_sz;
        const uint32_t bb = bs_base + buf * b_sz;
#pragma unroll
        for (int i = 0; i < 2; i++) {
            int e = tid + i * 256;         // < 512
            int r = e >> 3, c = e & 7;
            cpa16(ab + (r * ASTR + c * 8) * 2, Ag + (size_t)(m0 + r) * 96 + k0u + c);
        }
#pragma unroll
        for (int i = 0; i < 3; i++) {
            int e = tid + i * 256;
            if (e < 640) {
                int r = e >> 3, c = e & 7;
                cpa16(bb + (r * ASTR + c * 8) * 2, Bg + (size_t)(n0 + r) * 96 + k0u + c);
            }
        }
        asm volatile("cp.async.commit_group;" ::: "memory");
    };

    load_stage(0, 0);

    for (int s = 0; s < NSTAGE; s++) {
        if (s + 1 < NSTAGE) {
            load_stage(s + 1, (s + 1) & 1);
            asm volatile("cp.async.wait_group 1;" ::: "memory");
        } else {
            asm volatile("cp.async.wait_group 0;" ::: "memory");
        }
        __syncthreads();

        const uint32_t abuf = (uint32_t)(s & 1) * a_sz;
        const uint32_t bbuf = (uint32_t)(s & 1) * b_sz;
#pragma unroll
        for (int kk = 0; kk < BK; kk += 16) {
            uint32_t afr[4], bfr[5][2], bq[4];
            ldm_x4(afr, a_addr + abuf + kk * 2);
            ldm_x4(bq, b_addr4 + bbuf + kk * 2);            // n-tiles 0,1
            bfr[0][0] = bq[0]; bfr[0][1] = bq[1];
            bfr[1][0] = bq[2]; bfr[1][1] = bq[3];
            ldm_x4(bq, b_addr4 + bbuf + (16 * ASTR + kk) * 2); // n-tiles 2,3
            bfr[2][0] = bq[0]; bfr[2][1] = bq[1];
            bfr[3][0] = bq[2]; bfr[3][1] = bq[3];
            ldm_x2(bfr[4], b_addr2 + bbuf + kk * 2);        // n-tile 4
#pragma unroll
            for (int ni = 0; ni < 5; ni++)
                mma_f16(acc[ni], afr, bfr[ni]);
        }
        __syncthreads();
    }

    // ---- epilogue: float2 stores, all indices in-bounds by construction ----
#pragma unroll
    for (int ni = 0; ni < 5; ni++) {
        int r = m0 + wm * 16 + g;
        int c = n0 + wn * 40 + ni * 8 + tg * 2;
        *(float2*)(out + (size_t)r * NOUT + c) = make_float2(acc[ni][0], acc[ni][1]);
        *(float2*)(out + (size_t)(r + 8) * NOUT + c) = make_float2(acc[ni][2], acc[ni][3]);
    }
}

// =============================================================================
// launch
// =============================================================================
extern "C" void kernel_launch(void* const* d_in, const int* in_sizes, int n_in,
                              void* d_out, int out_size) {
    // metadata order: subwords, bert_lens, bert_mask, hidden_states,
    //                 mix_weights, gamma, proj_w
    const int*   lens  = (const int*)d_in[1];
    const float* hs    = (const float*)d_in[3];
    const float* mixw  = (const float*)d_in[4];
    const float* gamma = (const float*)d_in[5];
    const float* projw = (const float*)d_in[6];
    float*       out   = (float*)d_out;

    prep_kernel<<<32 + NOUT * H / 4 / 256, 256>>>(lens, mixw, gamma, projw);
    pool_kernel<<<NWORDS, H4>>>(hs, lens);
    gemm_kernel<<<dim3(NWORDS / BM, NOUT / 80), 256>>>(out);
}

// round 14
// speedup vs baseline: 1.1212x; 1.0137x over previous
#include <cuda_runtime.h>
#include <cuda_fp16.h>
#include <cstdint>

// Problem constants
#define B    32
#define SW   512
#define SL   256
#define H    768
#define NL   4
#define NOUT 400
#define NWORDS (B * SL)          // 8192
#define H4   (H / 4)             // 192 float4 per row

// ---------------- scratch (static device globals; no allocations) ------------
__device__ __half g_Ah[NWORDS * H];        // pooled fp16 (12.6 MB)
__device__ __half g_Bh[NOUT * H];          // proj_w fp16

// =============================================================================
// Kernel 1: pool — fused: proj_w conversion (blocks 0..399), per-block start
// computation (block reduction over lens), softmax weights (recomputed),
// layer mix + ragged mean, fp16 output row.
// One block per word, 192 threads.
// =============================================================================
__global__ __launch_bounds__(H4) void pool_kernel(
    const float* __restrict__ hs,          // [NL, B, SW, H]
    const int* __restrict__ lens,          // [B, SL]
    const float* __restrict__ mixw,        // [NL]
    const float* __restrict__ gamma,       // [1]
    const float* __restrict__ projw)       // [NOUT, H]
{
    const int wi = blockIdx.x;             // word index in [0, NWORDS)
    const int b  = wi >> 8;
    const int t  = threadIdx.x;            // 0..191

    // ---- side job: proj_w -> fp16 (blocks 0..399, one float4/thread) ----
    if (wi < 400) {
        const int i = wi * H4 + t;         // 400*192 = 76800 exactly
        float4 v = ((const float4*)projw)[i];
        __half2 p0 = __floats2half2_rn(v.x, v.y);
        __half2 p1 = __floats2half2_rn(v.z, v.w);
        uint2 pk;
        pk.x = *(uint32_t*)&p0;
        pk.y = *(uint32_t*)&p1;
        ((uint2*)g_Bh)[i] = pk;
    }

    // ---- start[wi] = sum(lens[b, :j]) via block reduction (exact int sum) ----
    const int j = wi & 255;
    int partial = 0;
    for (int i = t; i < j; i += H4) partial += lens[(b << 8) + i];
#pragma unroll
    for (int off = 16; off > 0; off >>= 1)
        partial += __shfl_down_sync(0xFFFFFFFFu, partial, off);
    __shared__ int wsum[6];
    if ((t & 31) == 0) wsum[t >> 5] = partial;
    __syncthreads();
    const int start = wsum[0] + wsum[1] + wsum[2] + wsum[3] + wsum[4] + wsum[5];

    const int len = lens[wi];
    const int end = min(start + len, SW);

    // ---- softmax weights (recomputed per block; 4 exps, free on BW-bound) ----
    const float mw0 = mixw[0], mw1 = mixw[1], mw2 = mixw[2], mw3 = mixw[3];
    const float mx = fmaxf(fmaxf(mw0, mw1), fmaxf(mw2, mw3));
    const float e0 = __expf(mw0 - mx), e1 = __expf(mw1 - mx);
    const float e2 = __expf(mw2 - mx), e3 = __expf(mw3 - mx);
    const float sinv = gamma[0] / (e0 + e1 + e2 + e3);
    const float w0 = e0 * sinv, w1 = e1 * sinv, w2 = e2 * sinv, w3 = e3 * sinv;

    // ---- mix + mean over the word's subwords ----
    const size_t lstride4 = (size_t)B * SW * H4;
    float4 acc = make_float4(0.f, 0.f, 0.f, 0.f);
    for (int p = start; p < end; p++) {
        const float4* base = (const float4*)hs + ((size_t)b * SW + p) * H4 + t;
        float4 v0 = base[0 * lstride4];
        float4 v1 = base[1 * lstride4];
        float4 v2 = base[2 * lstride4];
        float4 v3 = base[3 * lstride4];
        acc.x += w0 * v0.x + w1 * v1.x + w2 * v2.x + w3 * v3.x;
        acc.y += w0 * v0.y + w1 * v1.y + w2 * v2.y + w3 * v3.y;
        acc.z += w0 * v0.z + w1 * v1.z + w2 * v2.z + w3 * v3.z;
        acc.w += w0 * v0.w + w1 * v1.w + w2 * v2.w + w3 * v3.w;
    }
    const float inv = 1.0f / (float)max(len, 1);

    __half2 p0 = __floats2half2_rn(acc.x * inv, acc.y * inv);
    __half2 p1 = __floats2half2_rn(acc.z * inv, acc.w * inv);
    uint2 pk;
    pk.x = *(uint32_t*)&p0;
    pk.y = *(uint32_t*)&p1;
    ((uint2*)g_Ah)[(size_t)wi * 192 + t] = pk;
}

// =============================================================================
// Kernel 2: GEMM out[8192,400] = A[8192,768]fp16 @ W[400,768]^T fp16, fp32 acc.
// BM=64, BN=80, BK=64, 256 threads (8 warps 4x2: 16 rows x 40 cols each).
// cp.async double buffer (41.5KB smem), launch_bounds(256,4) -> 4 CTAs/SM,
// grid (128,5)=640 CTAs. Padded stride 72 halfs -> conflict-free ldmatrix.
// =============================================================================
#define BM 64
#define BK 64
#define ASTR 72                             // fp16 stride (144B)
#define NSTAGE (H / BK)                     // 12

__device__ __forceinline__ uint32_t smem_u32(const void* p) {
    uint32_t a;
    asm("{ .reg .u64 t; cvta.to.shared.u64 t, %1; cvt.u32.u64 %0, t; }" : "=r"(a) : "l"(p));
    return a;
}
__device__ __forceinline__ void ldm_x4(uint32_t* r, uint32_t addr) {
    asm volatile("ldmatrix.sync.aligned.m8n8.x4.shared.b16 {%0,%1,%2,%3}, [%4];"
        : "=r"(r[0]), "=r"(r[1]), "=r"(r[2]), "=r"(r[3]) : "r"(addr));
}
__device__ __forceinline__ void ldm_x2(uint32_t* r, uint32_t addr) {
    asm volatile("ldmatrix.sync.aligned.m8n8.x2.shared.b16 {%0,%1}, [%2];"
        : "=r"(r[0]), "=r"(r[1]) : "r"(addr));
}
__device__ __forceinline__ void mma_f16(float* d, const uint32_t* a, const uint32_t* b) {
    asm volatile(
        "mma.sync.aligned.m16n8k16.row.col.f32.f16.f16.f32 "
        "{%0,%1,%2,%3}, {%4,%5,%6,%7}, {%8,%9}, {%0,%1,%2,%3};"
        : "+f"(d[0]), "+f"(d[1]), "+f"(d[2]), "+f"(d[3])
        : "r"(a[0]), "r"(a[1]), "r"(a[2]), "r"(a[3]), "r"(b[0]), "r"(b[1]));
}
__device__ __forceinline__ void cpa16(uint32_t saddr, const void* g) {
    asm volatile("cp.async.cg.shared.global [%0], [%1], 16;" :: "r"(saddr), "l"(g) : "memory");
}

__global__ __launch_bounds__(256, 4) void gemm_kernel(float* __restrict__ out)
{
    __shared__ __half As[2][BM][ASTR];      // 2 * 9216 B
    __shared__ __half Bs[2][80][ASTR];      // 2 * 11520 B  -> 41472 total

    const int tid  = threadIdx.x;
    const int lane = tid & 31;
    const int warp = tid >> 5;
    const int wm   = warp & 3;             // 0..3 -> 16-row slice
    const int wn   = warp >> 2;            // 0..1 -> 40-col slice
    const int m0   = blockIdx.x * BM;
    const int n0   = blockIdx.y * 80;

    const int g  = lane >> 2;
    const int tg = lane & 3;

    const uint32_t as_base = smem_u32(As);
    const uint32_t bs_base = smem_u32(Bs);
    const uint32_t a_sz = BM * ASTR * 2;   // bytes per A buffer
    const uint32_t b_sz = 80 * ASTR * 2;

    const uint32_t a_addr = as_base +
        (((wm * 16) + (lane & 15)) * ASTR + (lane >> 4) * 8) * 2;
    const uint32_t b_addr4 = bs_base +
        ((wn * 40 + ((lane >> 4) & 1) * 8 + (lane & 7)) * ASTR
         + ((lane >> 3) & 1) * 8) * 2;
    const uint32_t b_addr2 = bs_base +
        ((wn * 40 + 32 + (lane & 7)) * ASTR + ((lane >> 3) & 1) * 8) * 2;

    float acc[5][4];
#pragma unroll
    for (int ni = 0; ni < 5; ni++)
#pragma unroll
        for (int r = 0; r < 4; r++) acc[ni][r] = 0.f;

    const uint4* Ag = (const uint4*)g_Ah;  // row stride 96 uint4
    const uint4* Bg = (const uint4*)g_Bh;

    auto load_stage = [&](int s, int buf) {
        const int k0u = s * 8;             // BK/8 uint4 per stage
        const uint32_t ab = as_base + buf * a_sz;
        const uint32_t bb = bs_base + buf * b_sz;
#pragma unroll
        for (int i = 0; i < 2; i++) {
            int e = tid + i * 256;         // < 512
            int r = e >> 3, c = e & 7;
            cpa16(ab + (r * ASTR + c * 8) * 2, Ag + (size_t)(m0 + r) * 96 + k0u + c);
        }
#pragma unroll
        for (int i = 0; i < 3; i++) {
            int e = tid + i * 256;
            if (e < 640) {
                int r = e >> 3, c = e & 7;
                cpa16(bb + (r * ASTR + c * 8) * 2, Bg + (size_t)(n0 + r) * 96 + k0u + c);
            }
        }
        asm volatile("cp.async.commit_group;" ::: "memory");
    };

    load_stage(0, 0);

    for (int s = 0; s < NSTAGE; s++) {
        if (s + 1 < NSTAGE) {
            load_stage(s + 1, (s + 1) & 1);
            asm volatile("cp.async.wait_group 1;" ::: "memory");
        } else {
            asm volatile("cp.async.wait_group 0;" ::: "memory");
        }
        __syncthreads();

        const uint32_t abuf = (uint32_t)(s & 1) * a_sz;
        const uint32_t bbuf = (uint32_t)(s & 1) * b_sz;
#pragma unroll
        for (int kk = 0; kk < BK; kk += 16) {
            uint32_t afr[4], bfr[5][2], bq[4];
            ldm_x4(afr, a_addr + abuf + kk * 2);
            ldm_x4(bq, b_addr4 + bbuf + kk * 2);            // n-tiles 0,1
            bfr[0][0] = bq[0]; bfr[0][1] = bq[1];
            bfr[1][0] = bq[2]; bfr[1][1] = bq[3];
            ldm_x4(bq, b_addr4 + bbuf + (16 * ASTR + kk) * 2); // n-tiles 2,3
            bfr[2][0] = bq[0]; bfr[2][1] = bq[1];
            bfr[3][0] = bq[2]; bfr[3][1] = bq[3];
            ldm_x2(bfr[4], b_addr2 + bbuf + kk * 2);        // n-tile 4
#pragma unroll
            for (int ni = 0; ni < 5; ni++)
                mma_f16(acc[ni], afr, bfr[ni]);
        }
        __syncthreads();
    }

    // ---- epilogue: float2 stores, all indices in-bounds by construction ----
#pragma unroll
    for (int ni = 0; ni < 5; ni++) {
        int r = m0 + wm * 16 + g;
        int c = n0 + wn * 40 + ni * 8 + tg * 2;
        *(float2*)(out + (size_t)r * NOUT + c) = make_float2(acc[ni][0], acc[ni][1]);
        *(float2*)(out + (size_t)(r + 8) * NOUT + c) = make_float2(acc[ni][2], acc[ni][3]);
    }
}

// =============================================================================
// launch — 2 kernels only
// =============================================================================
extern "C" void kernel_launch(void* const* d_in, const int* in_sizes, int n_in,
                              void* d_out, int out_size) {
    // metadata order: subwords, bert_lens, bert_mask, hidden_states,
    //                 mix_weights, gamma, proj_w
    const int*   lens  = (const int*)d_in[1];
    const float* hs    = (const float*)d_in[3];
    const float* mixw  = (const float*)d_in[4];
    const float* gamma = (const float*)d_in[5];
    const float* projw = (const float*)d_in[6];
    float*       out   = (float*)d_out;

    pool_kernel<<<NWORDS, H4>>>(hs, lens, mixw, gamma, projw);
    gemm_kernel<<<dim3(NWORDS / BM, NOUT / 80), 256>>>(out);
}

// round 16
// speedup vs baseline: 1.1368x; 1.0139x over previous
#include <cuda_runtime.h>
#include <cuda_fp16.h>
#include <cstdint>

// Problem constants
#define B    32
#define SW   512
#define SL   256
#define H    768
#define NL   4
#define NOUT 400
#define NWORDS (B * SL)          // 8192
#define H4   (H / 4)             // 192 float4 per row

// ---------------- scratch (static device globals; no allocations) ------------
__device__ __half g_Ah[NWORDS * H];        // pooled fp16 (12.6 MB)
__device__ __half g_Bh[NOUT * H];          // proj_w fp16

// =============================================================================
// Kernel 1: pool — fused: proj_w conversion (blocks 0..399), per-block start
// computation (block reduction over lens), softmax weights (recomputed),
// layer mix + ragged mean, fp16 output row. One block per word, 192 threads.
// =============================================================================
__global__ __launch_bounds__(H4) void pool_kernel(
    const float* __restrict__ hs,          // [NL, B, SW, H]
    const int* __restrict__ lens,          // [B, SL]
    const float* __restrict__ mixw,        // [NL]
    const float* __restrict__ gamma,       // [1]
    const float* __restrict__ projw)       // [NOUT, H]
{
    const int wi = blockIdx.x;             // word index in [0, NWORDS)
    const int b  = wi >> 8;
    const int t  = threadIdx.x;            // 0..191

    // ---- side job: proj_w -> fp16 (blocks 0..399, one float4/thread) ----
    if (wi < 400) {
        const int i = wi * H4 + t;         // 400*192 = 76800 exactly
        float4 v = ((const float4*)projw)[i];
        __half2 p0 = __floats2half2_rn(v.x, v.y);
        __half2 p1 = __floats2half2_rn(v.z, v.w);
        uint2 pk;
        pk.x = *(uint32_t*)&p0;
        pk.y = *(uint32_t*)&p1;
        ((uint2*)g_Bh)[i] = pk;
    }

    // ---- start[wi] = sum(lens[b, :j]) via block reduction (exact int sum) ----
    const int j = wi & 255;
    int partial = 0;
    for (int i = t; i < j; i += H4) partial += lens[(b << 8) + i];
#pragma unroll
    for (int off = 16; off > 0; off >>= 1)
        partial += __shfl_down_sync(0xFFFFFFFFu, partial, off);
    __shared__ int wsum[6];
    if ((t & 31) == 0) wsum[t >> 5] = partial;
    __syncthreads();
    const int start = wsum[0] + wsum[1] + wsum[2] + wsum[3] + wsum[4] + wsum[5];

    const int len = lens[wi];
    const int end = min(start + len, SW);

    // ---- softmax weights (recomputed per block) ----
    const float mw0 = mixw[0], mw1 = mixw[1], mw2 = mixw[2], mw3 = mixw[3];
    const float mx = fmaxf(fmaxf(mw0, mw1), fmaxf(mw2, mw3));
    const float e0 = __expf(mw0 - mx), e1 = __expf(mw1 - mx);
    const float e2 = __expf(mw2 - mx), e3 = __expf(mw3 - mx);
    const float sinv = gamma[0] / (e0 + e1 + e2 + e3);
    const float w0 = e0 * sinv, w1 = e1 * sinv, w2 = e2 * sinv, w3 = e3 * sinv;

    // ---- mix + mean over the word's subwords (unrolled x2 for MLP) ----
    const size_t lstride4 = (size_t)B * SW * H4;
    float4 acc = make_float4(0.f, 0.f, 0.f, 0.f);
    int p = start;
    for (; p + 2 <= end; p += 2) {
        const float4* b0 = (const float4*)hs + ((size_t)b * SW + p) * H4 + t;
        const float4* b1 = b0 + H4;
        float4 v0 = b0[0 * lstride4], u0 = b1[0 * lstride4];
        float4 v1 = b0[1 * lstride4], u1 = b1[1 * lstride4];
        float4 v2 = b0[2 * lstride4], u2 = b1[2 * lstride4];
        float4 v3 = b0[3 * lstride4], u3 = b1[3 * lstride4];
        acc.x += w0 * (v0.x + u0.x) + w1 * (v1.x + u1.x) + w2 * (v2.x + u2.x) + w3 * (v3.x + u3.x);
        acc.y += w0 * (v0.y + u0.y) + w1 * (v1.y + u1.y) + w2 * (v2.y + u2.y) + w3 * (v3.y + u3.y);
        acc.z += w0 * (v0.z + u0.z) + w1 * (v1.z + u1.z) + w2 * (v2.z + u2.z) + w3 * (v3.z + u3.z);
        acc.w += w0 * (v0.w + u0.w) + w1 * (v1.w + u1.w) + w2 * (v2.w + u2.w) + w3 * (v3.w + u3.w);
    }
    if (p < end) {
        const float4* base = (const float4*)hs + ((size_t)b * SW + p) * H4 + t;
        float4 v0 = base[0 * lstride4];
        float4 v1 = base[1 * lstride4];
        float4 v2 = base[2 * lstride4];
        float4 v3 = base[3 * lstride4];
        acc.x += w0 * v0.x + w1 * v1.x + w2 * v2.x + w3 * v3.x;
        acc.y += w0 * v0.y + w1 * v1.y + w2 * v2.y + w3 * v3.y;
        acc.z += w0 * v0.z + w1 * v1.z + w2 * v2.z + w3 * v3.z;
        acc.w += w0 * v0.w + w1 * v1.w + w2 * v2.w + w3 * v3.w;
    }
    const float inv = 1.0f / (float)max(len, 1);

    __half2 p0 = __floats2half2_rn(acc.x * inv, acc.y * inv);
    __half2 p1 = __floats2half2_rn(acc.z * inv, acc.w * inv);
    uint2 pk;
    pk.x = *(uint32_t*)&p0;
    pk.y = *(uint32_t*)&p1;
    ((uint2*)g_Ah)[(size_t)wi * 192 + t] = pk;
}

// =============================================================================
// Kernel 2: GEMM out[8192,400] = A[8192,768]fp16 @ W[400,768]^T fp16, fp32 acc.
// BM=64, BN=80, BK=32, 256 threads (8 warps 4x2: 16 rows x 40 cols each).
// 4-deep cp.async ring (46KB smem), 1 __syncthreads per stage, wait_group 2
// -> loads run 3 stages ahead. launch_bounds(256,4). Exact tiling grid(128,5).
// =============================================================================
#define BM 64
#define BK 32
#define NBUF 4
#define ASTR 40                             // fp16 stride (80B) - conflict-free
#define NSTAGE (H / BK)                     // 24

__device__ __forceinline__ uint32_t smem_u32(const void* p) {
    uint32_t a;
    asm("{ .reg .u64 t; cvta.to.shared.u64 t, %1; cvt.u32.u64 %0, t; }" : "=r"(a) : "l"(p));
    return a;
}
__device__ __forceinline__ void ldm_x4(uint32_t* r, uint32_t addr) {
    asm volatile("ldmatrix.sync.aligned.m8n8.x4.shared.b16 {%0,%1,%2,%3}, [%4];"
        : "=r"(r[0]), "=r"(r[1]), "=r"(r[2]), "=r"(r[3]) : "r"(addr));
}
__device__ __forceinline__ void ldm_x2(uint32_t* r, uint32_t addr) {
    asm volatile("ldmatrix.sync.aligned.m8n8.x2.shared.b16 {%0,%1}, [%2];"
        : "=r"(r[0]), "=r"(r[1]) : "r"(addr));
}
__device__ __forceinline__ void mma_f16(float* d, const uint32_t* a, const uint32_t* b) {
    asm volatile(
        "mma.sync.aligned.m16n8k16.row.col.f32.f16.f16.f32 "
        "{%0,%1,%2,%3}, {%4,%5,%6,%7}, {%8,%9}, {%0,%1,%2,%3};"
        : "+f"(d[0]), "+f"(d[1]), "+f"(d[2]), "+f"(d[3])
        : "r"(a[0]), "r"(a[1]), "r"(a[2]), "r"(a[3]), "r"(b[0]), "r"(b[1]));
}
__device__ __forceinline__ void cpa16(uint32_t saddr, const void* g) {
    asm volatile("cp.async.cg.shared.global [%0], [%1], 16;" :: "r"(saddr), "l"(g) : "memory");
}
__device__ __forceinline__ void cpa_commit() {
    asm volatile("cp.async.commit_group;" ::: "memory");
}

__global__ __launch_bounds__(256, 4) void gemm_kernel(float* __restrict__ out)
{
    __shared__ __half As[NBUF][BM][ASTR];   // 4 * 5120 B
    __shared__ __half Bs[NBUF][80][ASTR];   // 4 * 6400 B  -> 46080 total

    const int tid  = threadIdx.x;
    const int lane = tid & 31;
    const int warp = tid >> 5;
    const int wm   = warp & 3;             // 0..3 -> 16-row slice
    const int wn   = warp >> 2;            // 0..1 -> 40-col slice
    const int m0   = blockIdx.x * BM;
    const int n0   = blockIdx.y * 80;

    const int g  = lane >> 2;
    const int tg = lane & 3;

    const uint32_t as_base = smem_u32(As);
    const uint32_t bs_base = smem_u32(Bs);
    const uint32_t a_sz = BM * ASTR * 2;   // 5120 B per A buffer
    const uint32_t b_sz = 80 * ASTR * 2;   // 6400 B per B buffer

    const uint32_t a_addr = as_base +
        (((wm * 16) + (lane & 15)) * ASTR + (lane >> 4) * 8) * 2;
    const uint32_t b_addr4 = bs_base +
        ((wn * 40 + ((lane >> 4) & 1) * 8 + (lane & 7)) * ASTR
         + ((lane >> 3) & 1) * 8) * 2;
    const uint32_t b_addr2 = bs_base +
        ((wn * 40 + 32 + (lane & 7)) * ASTR + ((lane >> 3) & 1) * 8) * 2;

    float acc[5][4];
#pragma unroll
    for (int ni = 0; ni < 5; ni++)
#pragma unroll
        for (int r = 0; r < 4; r++) acc[ni][r] = 0.f;

    const uint4* Ag = (const uint4*)g_Ah;  // row stride 96 uint4
    const uint4* Bg = (const uint4*)g_Bh;

    // ---- stage loader: A 64x4 uint4 (256), B 80x4 uint4 (320); commits ----
    auto load_stage = [&](int s) {
        const int k0u = s * 4;             // BK/8 uint4 per stage
        const int buf = s & (NBUF - 1);
        const uint32_t ab = as_base + buf * a_sz;
        const uint32_t bb = bs_base + buf * b_sz;
        {
            int r = tid >> 2, c = tid & 3; // 256 exactly
            cpa16(ab + (r * ASTR + c * 8) * 2, Ag + (size_t)(m0 + r) * 96 + k0u + c);
        }
#pragma unroll
        for (int i = 0; i < 2; i++) {
            int e = tid + i * 256;
            if (e < 320) {
                int r = e >> 2, c = e & 3;
                cpa16(bb + (r * ASTR + c * 8) * 2, Bg + (size_t)(n0 + r) * 96 + k0u + c);
            }
        }
        cpa_commit();
    };

    load_stage(0);
    load_stage(1);
    load_stage(2);

    for (int s = 0; s < NSTAGE; s++) {
        // stages 0..s complete once <=2 groups pending (3 prologue + 1/iter)
        asm volatile("cp.async.wait_group 2;" ::: "memory");
        __syncthreads();                   // visibility + WAR protect buf (s+3)%4

        if (s + 3 < NSTAGE) load_stage(s + 3);
        else cpa_commit();                 // keep group count invariant

        const uint32_t abuf = (uint32_t)(s & (NBUF - 1)) * a_sz;
        const uint32_t bbuf = (uint32_t)(s & (NBUF - 1)) * b_sz;
#pragma unroll
        for (int kk = 0; kk < BK; kk += 16) {
            uint32_t afr[4], bfr[5][2], bq[4];
            ldm_x4(afr, a_addr + abuf + kk * 2);
            ldm_x4(bq, b_addr4 + bbuf + kk * 2);            // n-tiles 0,1
            bfr[0][0] = bq[0]; bfr[0][1] = bq[1];
            bfr[1][0] = bq[2]; bfr[1][1] = bq[3];
            ldm_x4(bq, b_addr4 + bbuf + (16 * ASTR + kk) * 2); // n-tiles 2,3
            bfr[2][0] = bq[0]; bfr[2][1] = bq[1];
            bfr[3][0] = bq[2]; bfr[3][1] = bq[3];
            ldm_x2(bfr[4], b_addr2 + bbuf + kk * 2);        // n-tile 4
#pragma unroll
            for (int ni = 0; ni < 5; ni++)
                mma_f16(acc[ni], afr, bfr[ni]);
        }
    }

    // ---- epilogue: float2 stores, all indices in-bounds by construction ----
#pragma unroll
    for (int ni = 0; ni < 5; ni++) {
        int r = m0 + wm * 16 + g;
        int c = n0 + wn * 40 + ni * 8 + tg * 2;
        *(float2*)(out + (size_t)r * NOUT + c) = make_float2(acc[ni][0], acc[ni][1]);
        *(float2*)(out + (size_t)(r + 8) * NOUT + c) = make_float2(acc[ni][2], acc[ni][3]);
    }
}

// =============================================================================
// launch — 2 kernels only
// =============================================================================
extern "C" void kernel_launch(void* const* d_in, const int* in_sizes, int n_in,
                              void* d_out, int out_size) {
    // metadata order: subwords, bert_lens, bert_mask, hidden_states,
    //                 mix_weights, gamma, proj_w
    const int*   lens  = (const int*)d_in[1];
    const float* hs    = (const float*)d_in[3];
    const float* mixw  = (const float*)d_in[4];
    const float* gamma = (const float*)d_in[5];
    const float* projw = (const float*)d_in[6];
    float*       out   = (float*)d_out;

    pool_kernel<<<NWORDS, H4>>>(hs, lens, mixw, gamma, projw);
    gemm_kernel<<<dim3(NWORDS / BM, NOUT / 80), 256>>>(out);
}

// round 17
// speedup vs baseline: 1.2071x; 1.0619x over previous
#include <cuda_runtime.h>
#include <cuda_fp16.h>
#include <cstdint>

// Problem constants
#define B    32
#define SW   512
#define SL   256
#define H    768
#define NL   4
#define NOUT 400
#define NWORDS (B * SL)          // 8192
#define H4   (H / 4)             // 192 float4 per row

// ---------------- scratch (static device globals; no allocations) ------------
__device__ __half g_Ah[NWORDS * H];        // pooled fp16 (12.6 MB)
__device__ __half g_Bh[NOUT * H];          // proj_w fp16

// =============================================================================
// Kernel 1: pool — fused: proj_w conversion (blocks 0..399), per-block start
// computation (block reduction over lens), softmax weights (recomputed),
// layer mix + ragged mean, fp16 output row. One block per word, 192 threads.
// =============================================================================
__global__ __launch_bounds__(H4) void pool_kernel(
    const float* __restrict__ hs,          // [NL, B, SW, H]
    const int* __restrict__ lens,          // [B, SL]
    const float* __restrict__ mixw,        // [NL]
    const float* __restrict__ gamma,       // [1]
    const float* __restrict__ projw)       // [NOUT, H]
{
    const int wi = blockIdx.x;             // word index in [0, NWORDS)
    const int b  = wi >> 8;
    const int t  = threadIdx.x;            // 0..191

    // ---- side job: proj_w -> fp16 (blocks 0..399, one float4/thread) ----
    if (wi < 400) {
        const int i = wi * H4 + t;         // 400*192 = 76800 exactly
        float4 v = ((const float4*)projw)[i];
        __half2 p0 = __floats2half2_rn(v.x, v.y);
        __half2 p1 = __floats2half2_rn(v.z, v.w);
        uint2 pk;
        pk.x = *(uint32_t*)&p0;
        pk.y = *(uint32_t*)&p1;
        ((uint2*)g_Bh)[i] = pk;
    }

    // ---- start[wi] = sum(lens[b, :j]) via block reduction (exact int sum) ----
    const int j = wi & 255;
    int partial = 0;
    for (int i = t; i < j; i += H4) partial += lens[(b << 8) + i];
#pragma unroll
    for (int off = 16; off > 0; off >>= 1)
        partial += __shfl_down_sync(0xFFFFFFFFu, partial, off);
    __shared__ int wsum[6];
    if ((t & 31) == 0) wsum[t >> 5] = partial;
    __syncthreads();
    const int start = wsum[0] + wsum[1] + wsum[2] + wsum[3] + wsum[4] + wsum[5];

    const int len = lens[wi];
    const int end = min(start + len, SW);

    // ---- softmax weights (recomputed per block) ----
    const float mw0 = mixw[0], mw1 = mixw[1], mw2 = mixw[2], mw3 = mixw[3];
    const float mx = fmaxf(fmaxf(mw0, mw1), fmaxf(mw2, mw3));
    const float e0 = __expf(mw0 - mx), e1 = __expf(mw1 - mx);
    const float e2 = __expf(mw2 - mx), e3 = __expf(mw3 - mx);
    const float sinv = gamma[0] / (e0 + e1 + e2 + e3);
    const float w0 = e0 * sinv, w1 = e1 * sinv, w2 = e2 * sinv, w3 = e3 * sinv;

    // ---- mix + mean over the word's subwords (unrolled x2 for MLP) ----
    const size_t lstride4 = (size_t)B * SW * H4;
    float4 acc = make_float4(0.f, 0.f, 0.f, 0.f);
    int p = start;
    for (; p + 2 <= end; p += 2) {
        const float4* b0 = (const float4*)hs + ((size_t)b * SW + p) * H4 + t;
        const float4* b1 = b0 + H4;
        float4 v0 = b0[0 * lstride4], u0 = b1[0 * lstride4];
        float4 v1 = b0[1 * lstride4], u1 = b1[1 * lstride4];
        float4 v2 = b0[2 * lstride4], u2 = b1[2 * lstride4];
        float4 v3 = b0[3 * lstride4], u3 = b1[3 * lstride4];
        acc.x += w0 * (v0.x + u0.x) + w1 * (v1.x + u1.x) + w2 * (v2.x + u2.x) + w3 * (v3.x + u3.x);
        acc.y += w0 * (v0.y + u0.y) + w1 * (v1.y + u1.y) + w2 * (v2.y + u2.y) + w3 * (v3.y + u3.y);
        acc.z += w0 * (v0.z + u0.z) + w1 * (v1.z + u1.z) + w2 * (v2.z + u2.z) + w3 * (v3.z + u3.z);
        acc.w += w0 * (v0.w + u0.w) + w1 * (v1.w + u1.w) + w2 * (v2.w + u2.w) + w3 * (v3.w + u3.w);
    }
    if (p < end) {
        const float4* base = (const float4*)hs + ((size_t)b * SW + p) * H4 + t;
        float4 v0 = base[0 * lstride4];
        float4 v1 = base[1 * lstride4];
        float4 v2 = base[2 * lstride4];
        float4 v3 = base[3 * lstride4];
        acc.x += w0 * v0.x + w1 * v1.x + w2 * v2.x + w3 * v3.x;
        acc.y += w0 * v0.y + w1 * v1.y + w2 * v2.y + w3 * v3.y;
        acc.z += w0 * v0.z + w1 * v1.z + w2 * v2.z + w3 * v3.z;
        acc.w += w0 * v0.w + w1 * v1.w + w2 * v2.w + w3 * v3.w;
    }
    const float inv = 1.0f / (float)max(len, 1);

    __half2 p0 = __floats2half2_rn(acc.x * inv, acc.y * inv);
    __half2 p1 = __floats2half2_rn(acc.z * inv, acc.w * inv);
    uint2 pk;
    pk.x = *(uint32_t*)&p0;
    pk.y = *(uint32_t*)&p1;
    ((uint2*)g_Ah)[(size_t)wi * 192 + t] = pk;
}

// =============================================================================
// Kernel 2: GEMM out[8192,400] = A[8192,768]fp16 @ W[400,768]^T fp16, fp32 acc.
// BM=64, BN=80, BK=32. 128 threads = 4 warps (2x2), warp tile 32x40
// (A-fragment reuse doubled: 115 B LDSM per MMA vs 179 before).
// 3-deep cp.async ring (34.6KB smem), launch_bounds(128,5) -> 5 CTAs/SM,
// capacity 740 >= grid 640 -> SINGLE WAVE. Exact tiling grid(128,5).
// =============================================================================
#define BM 64
#define BK 32
#define NBUF 3
#define ASTR 40                             // fp16 stride (80B) - conflict-free
#define NSTAGE (H / BK)                     // 24

__device__ __forceinline__ uint32_t smem_u32(const void* p) {
    uint32_t a;
    asm("{ .reg .u64 t; cvta.to.shared.u64 t, %1; cvt.u32.u64 %0, t; }" : "=r"(a) : "l"(p));
    return a;
}
__device__ __forceinline__ void ldm_x4(uint32_t* r, uint32_t addr) {
    asm volatile("ldmatrix.sync.aligned.m8n8.x4.shared.b16 {%0,%1,%2,%3}, [%4];"
        : "=r"(r[0]), "=r"(r[1]), "=r"(r[2]), "=r"(r[3]) : "r"(addr));
}
__device__ __forceinline__ void ldm_x2(uint32_t* r, uint32_t addr) {
    asm volatile("ldmatrix.sync.aligned.m8n8.x2.shared.b16 {%0,%1}, [%2];"
        : "=r"(r[0]), "=r"(r[1]) : "r"(addr));
}
__device__ __forceinline__ void mma_f16(float* d, const uint32_t* a, const uint32_t* b) {
    asm volatile(
        "mma.sync.aligned.m16n8k16.row.col.f32.f16.f16.f32 "
        "{%0,%1,%2,%3}, {%4,%5,%6,%7}, {%8,%9}, {%0,%1,%2,%3};"
        : "+f"(d[0]), "+f"(d[1]), "+f"(d[2]), "+f"(d[3])
        : "r"(a[0]), "r"(a[1]), "r"(a[2]), "r"(a[3]), "r"(b[0]), "r"(b[1]));
}
__device__ __forceinline__ void cpa16(uint32_t saddr, const void* g) {
    asm volatile("cp.async.cg.shared.global [%0], [%1], 16;" :: "r"(saddr), "l"(g) : "memory");
}
__device__ __forceinline__ void cpa_commit() {
    asm volatile("cp.async.commit_group;" ::: "memory");
}

__global__ __launch_bounds__(128, 5) void gemm_kernel(float* __restrict__ out)
{
    __shared__ __half As[NBUF][BM][ASTR];   // 3 * 5120 B
    __shared__ __half Bs[NBUF][80][ASTR];   // 3 * 6400 B  -> 34560 total

    const int tid  = threadIdx.x;
    const int lane = tid & 31;
    const int warp = tid >> 5;
    const int wm   = warp & 1;             // 0..1 -> 32-row slice
    const int wn   = warp >> 1;            // 0..1 -> 40-col slice
    const int m0   = blockIdx.x * BM;
    const int n0   = blockIdx.y * 80;

    const int g  = lane >> 2;
    const int tg = lane & 3;

    const uint32_t as_base = smem_u32(As);
    const uint32_t bs_base = smem_u32(Bs);
    const uint32_t a_sz = BM * ASTR * 2;   // 5120 B per A buffer
    const uint32_t b_sz = 80 * ASTR * 2;   // 6400 B per B buffer

    // A fragment addrs for the two m16 tiles of the 32-row slice
    const uint32_t a_addr0 = as_base +
        ((wm * 32 + (lane & 15)) * ASTR + (lane >> 4) * 8) * 2;
    const uint32_t a_addr1 = a_addr0 + 16 * ASTR * 2;
    // B x4 addr (n-tiles 0,1 / 2,3): row = wn*40 + ((lane>>4)&1)*8 + (lane&7)
    const uint32_t b_addr4 = bs_base +
        ((wn * 40 + ((lane >> 4) & 1) * 8 + (lane & 7)) * ASTR
         + ((lane >> 3) & 1) * 8) * 2;
    // B x2 addr (n-tile 4)
    const uint32_t b_addr2 = bs_base +
        ((wn * 40 + 32 + (lane & 7)) * ASTR + ((lane >> 3) & 1) * 8) * 2;

    float acc[2][5][4];
#pragma unroll
    for (int mi = 0; mi < 2; mi++)
#pragma unroll
        for (int ni = 0; ni < 5; ni++)
#pragma unroll
            for (int r = 0; r < 4; r++) acc[mi][ni][r] = 0.f;

    const uint4* Ag = (const uint4*)g_Ah;  // row stride 96 uint4
    const uint4* Bg = (const uint4*)g_Bh;

    // ---- stage loader: A 64x4 uint4 (256), B 80x4 uint4 (320); commits ----
    auto load_stage = [&](int s) {
        const int k0u = s * 4;             // BK/8 uint4 per stage
        const int buf = s % NBUF;
        const uint32_t ab = as_base + buf * a_sz;
        const uint32_t bb = bs_base + buf * b_sz;
#pragma unroll
        for (int i = 0; i < 2; i++) {      // 256 A vectors over 128 threads
            int e = tid + i * 128;
            int r = e >> 2, c = e & 3;
            cpa16(ab + (r * ASTR + c * 8) * 2, Ag + (size_t)(m0 + r) * 96 + k0u + c);
        }
#pragma unroll
        for (int i = 0; i < 3; i++) {      // 320 B vectors
            int e = tid + i * 128;
            if (e < 320) {
                int r = e >> 2, c = e & 3;
                cpa16(bb + (r * ASTR + c * 8) * 2, Bg + (size_t)(n0 + r) * 96 + k0u + c);
            }
        }
        cpa_commit();
    };

    load_stage(0);
    load_stage(1);

    for (int s = 0; s < NSTAGE; s++) {
        asm volatile("cp.async.wait_group 1;" ::: "memory");   // stage s done
        __syncthreads();                   // visibility + WAR protect buf (s+2)%3

        if (s + 2 < NSTAGE) load_stage(s + 2);
        else cpa_commit();                 // keep group count invariant

        const uint32_t abuf = (uint32_t)(s % NBUF) * a_sz;
        const uint32_t bbuf = (uint32_t)(s % NBUF) * b_sz;
#pragma unroll
        for (int kk = 0; kk < BK; kk += 16) {
            uint32_t afr[2][4], bfr[5][2], bq[4];
            ldm_x4(afr[0], a_addr0 + abuf + kk * 2);
            ldm_x4(afr[1], a_addr1 + abuf + kk * 2);
            ldm_x4(bq, b_addr4 + bbuf + kk * 2);            // n-tiles 0,1
            bfr[0][0] = bq[0]; bfr[0][1] = bq[1];
            bfr[1][0] = bq[2]; bfr[1][1] = bq[3];
            ldm_x4(bq, b_addr4 + bbuf + (16 * ASTR + kk) * 2); // n-tiles 2,3
            bfr[2][0] = bq[0]; bfr[2][1] = bq[1];
            bfr[3][0] = bq[2]; bfr[3][1] = bq[3];
            ldm_x2(bfr[4], b_addr2 + bbuf + kk * 2);        // n-tile 4
#pragma unroll
            for (int mi = 0; mi < 2; mi++)
#pragma unroll
                for (int ni = 0; ni < 5; ni++)
                    mma_f16(acc[mi][ni], afr[mi], bfr[ni]);
        }
    }

    // ---- epilogue: float2 stores, all indices in-bounds by construction ----
#pragma unroll
    for (int mi = 0; mi < 2; mi++) {
#pragma unroll
        for (int ni = 0; ni < 5; ni++) {
            int r = m0 + wm * 32 + mi * 16 + g;
            int c = n0 + wn * 40 + ni * 8 + tg * 2;
            *(float2*)(out + (size_t)r * NOUT + c) =
                make_float2(acc[mi][ni][0], acc[mi][ni][1]);
            *(float2*)(out + (size_t)(r + 8) * NOUT + c) =
                make_float2(acc[mi][ni][2], acc[mi][ni][3]);
        }
    }
}

// =============================================================================
// launch — 2 kernels only
// =============================================================================
extern "C" void kernel_launch(void* const* d_in, const int* in_sizes, int n_in,
                              void* d_out, int out_size) {
    // metadata order: subwords, bert_lens, bert_mask, hidden_states,
    //                 mix_weights, gamma, proj_w
    const int*   lens  = (const int*)d_in[1];
    const float* hs    = (const float*)d_in[3];
    const float* mixw  = (const float*)d_in[4];
    const float* gamma = (const float*)d_in[5];
    const float* projw = (const float*)d_in[6];
    float*       out   = (float*)d_out;

    pool_kernel<<<NWORDS, H4>>>(hs, lens, mixw, gamma, projw);
    gemm_kernel<<<dim3(NWORDS / BM, NOUT / 80), 128>>>(out);
}